// round 11
// baseline (speedup 1.0000x reference)
#include <cuda_runtime.h>
#include <cuda_bf16.h>

#define DD 128
#define HH 512
#define WW 512
#define THRESH 0.997f
#define KPK 131072
#define NB  65536                 // value buckets AND spatial cells (16*64*64)
#define NCH 64                    // scan chunks of 1024 buckets
#define CSLOTS 16                 // per-cell candidate capacity (lambda~1.5 -> safe)
#define CAND_CAP (1<<18)          // 262144
#define LOCAL_SORT 24             // per-bucket in-register sort capacity

// ------------- device scratch (static; all counters self-restore to 0) --------
__device__ unsigned c_cnt[NB];                // per-cell count   (zeroed by finalize)
__device__ uint2    c_data[NB * CSLOTS];      // (idx, valbits) per cell slot
__device__ unsigned g_ncand;                  // compact count    (zeroed by finalize)
__device__ uint2    g_cand[CAND_CAP];         // compact candidate list (idx, valbits)
__device__ unsigned g_cand_bucket[CAND_CAP];  // per-candidate bucket or INVALID
__device__ float4   g_pay[CAND_CAP];          // per-candidate output payload (peaks only)
__device__ unsigned g_hist[NB];               // per-bucket peak count (zeroed by scatter)
__device__ unsigned g_off[NB];                // within-chunk strictly-after offsets
__device__ unsigned b_chunk[NCH];
__device__ unsigned b_csuf[NCH];
__device__ unsigned g_done;                   // scan ticket (reset by last block)
__device__ unsigned g_total;                  // min(raw, KPK)
__device__ unsigned g_tot_raw;
__device__ unsigned g_sidx[KPK];              // voxel idx in rank position
__device__ float4   g_spay[KPK];              // payload in rank position

#define INVALID_B 0xFFFFFFFFu

__device__ __forceinline__ unsigned cell_of(unsigned idx) {
    unsigned z = idx >> 18, y = (idx >> 9) & 511u, x = idx & 511u;
    return ((z >> 3) << 12) | ((y >> 3) << 6) | (x >> 3);
}

// ---- kernel 1: stream volume; block-aggregated compact append + cell slots ----
__global__ void k_detect(const float* __restrict__ vol) {
    __shared__ uint2 s_cand[1024];
    __shared__ unsigned s_cnt, s_base;
    if (threadIdx.x == 0) s_cnt = 0u;
    __syncthreads();

    const float4* v4 = (const float4*)vol;
    unsigned tile = blockIdx.x * 2048u;
#pragma unroll
    for (int j = 0; j < 8; j++) {
        unsigned i = tile + j * 256u + threadIdx.x;
        float4 f = v4[i];
        unsigned base = i * 4u;
        float vv[4] = {f.x, f.y, f.z, f.w};
#pragma unroll
        for (int e = 0; e < 4; e++) {
            if (vv[e] > THRESH) {
                unsigned p = atomicAdd(&s_cnt, 1u);
                if (p < 1024u) s_cand[p] = make_uint2(base + (unsigned)e, __float_as_uint(vv[e]));
            }
        }
    }
    __syncthreads();
    unsigned cnt = min(s_cnt, 1024u);
    if (threadIdx.x == 0) s_base = atomicAdd(&g_ncand, cnt);
    __syncthreads();
    for (unsigned j = threadIdx.x; j < cnt; j += blockDim.x) {
        uint2 rec = s_cand[j];
        unsigned p = s_base + j;
        if (p < CAND_CAP) g_cand[p] = rec;
        unsigned c = cell_of(rec.x);
        unsigned slot = atomicAdd(&c_cnt[c], 1u);   // 65536 addrs: no contention
        if (slot < CSLOTS) c_data[c * CSLOTS + slot] = rec;
    }
}

// ---- kernel 2: verify 7^3 local max via cell probes, then compute payload -----
// A defeating neighbor (> v > 0.997) is itself a candidate, so only candidate
// records in the <=8 overlapping cells need checking. For surviving peaks the
// full centroid refinement + coordinate reconstruction is done right here
// (order-independent), producing the final float4 payload.
__global__ void k_verify_cent(const float* __restrict__ vol) {
    unsigned i = blockIdx.x * blockDim.x + threadIdx.x;
    unsigned n = min(g_ncand, (unsigned)CAND_CAP);
    if (i >= n) return;
    uint2 me = g_cand[i];
    unsigned idx = me.x;
    float v = __uint_as_float(me.y);
    int z = idx >> 18, y = (idx >> 9) & 511, x = idx & 511;

    int cz0 = max(z - 3, 0) >> 3, cz1 = min(z + 3, DD - 1) >> 3;
    int cy0 = max(y - 3, 0) >> 3, cy1 = min(y + 3, HH - 1) >> 3;
    int cx0 = max(x - 3, 0) >> 3, cx1 = min(x + 3, WW - 1) >> 3;
    bool peak = true;
    for (int cz = cz0; cz <= cz1 && peak; cz++)
    for (int cy = cy0; cy <= cy1 && peak; cy++)
    for (int cx = cx0; cx <= cx1 && peak; cx++) {
        unsigned c2 = ((unsigned)cz << 12) | ((unsigned)cy << 6) | (unsigned)cx;
        unsigned cn2 = min(c_cnt[c2], (unsigned)CSLOTS);
        unsigned b2 = c2 * CSLOTS;
        for (unsigned j = 0; j < cn2; j++) {
            uint2 r = c_data[b2 + j];
            if (__uint_as_float(r.y) > v) {
                int rz = r.x >> 18, ry = (r.x >> 9) & 511, rx = r.x & 511;
                if (abs(rz - z) <= 3 && abs(ry - y) <= 3 && abs(rx - x) <= 3) {
                    peak = false; break;
                }
            }
        }
    }
    if (!peak) { g_cand_bucket[i] = INVALID_B; return; }

    unsigned bucket = me.y & 0xFFFFu;   // monotone key: all peaks share top bits 0x3F7F
    atomicAdd(&g_hist[bucket], 1u);
    g_cand_bucket[i] = bucket;

    // centroid over the 7^3 patch: each x-run covered by three aligned float4
    // loads from a = clamp((x-3)&~3, 0, 500), out-of-window weight-masked
    // (matches the reference's zero padding).
    int a = max(x - 3, 0) & ~3;
    if (a > WW - 12) a = WW - 12;
    float s0 = 0.f, sx = 0.f, sy = 0.f, sz = 0.f;
#pragma unroll
    for (int dz = -3; dz <= 3; dz++) {
        int zz = z + dz;
        if ((unsigned)zz >= (unsigned)DD) continue;
        const float* pz = vol + ((unsigned)zz << 18);
#pragma unroll
        for (int dy = -3; dy <= 3; dy++) {
            int yy = y + dy;
            if ((unsigned)yy >= (unsigned)HH) continue;
            const float* rp = pz + ((unsigned)yy << 9);
            float4 A = *(const float4*)(rp + a);
            float4 B = *(const float4*)(rp + a + 4);
            float4 C = *(const float4*)(rp + a + 8);
            float vals[12] = {A.x, A.y, A.z, A.w, B.x, B.y, B.z, B.w, C.x, C.y, C.z, C.w};
            float rs0 = 0.f, rsx = 0.f;
#pragma unroll
            for (int e = 0; e < 12; e++) {
                int dx = a + e - x;
                bool in = (dx >= -3) && (dx <= 3);
                float vv = in ? vals[e] : 0.f;
                rs0 += vv;
                rsx += vv * (float)dx;
            }
            s0 += rs0;
            sx += rsx;
            sy += rs0 * (float)dy;
            sz += rs0 * (float)dz;
        }
    }
    float inv  = 1.f / s0;
    float xrec = ((float)x + sx * inv - 255.5f) * 0.1f;
    float yrec = ((float)y + sy * inv - 255.5f) * 0.1f;
    float zrec = ((float)z + sz * inv + 0.5f) * 0.02f - 2.0f;
    g_pay[i] = make_float4(xrec, yrec, zrec, v);
}

// ---- kernel 3: fused two-level suffix (descending) scan over 65536 buckets ----
__global__ void k_scan() {
    __shared__ unsigned s_h[1024];
    __shared__ unsigned s_w[8];
    __shared__ unsigned s_last;
    int t = threadIdx.x;
    unsigned base = blockIdx.x * 1024u;
#pragma unroll
    for (int j = 0; j < 4; j++) s_h[j * 256 + t] = g_hist[base + j * 256 + t];
    __syncthreads();
    unsigned h0 = s_h[t*4+0], h1 = s_h[t*4+1], h2 = s_h[t*4+2], h3 = s_h[t*4+3];
    unsigned sum4 = h0 + h1 + h2 + h3;
    unsigned v = sum4;
    int lane = t & 31, w = t >> 5;
#pragma unroll
    for (int d = 1; d < 32; d <<= 1) {
        unsigned o = __shfl_down_sync(0xFFFFFFFFu, v, d);
        if (lane + d < 32) v += o;
    }
    if (lane == 0) s_w[w] = v;
    __syncthreads();
    unsigned wafter = 0;
    for (int i = w + 1; i < 8; i++) wafter += s_w[i];
    unsigned run = wafter + (v - sum4);          // strictly-after, within chunk
    unsigned o3 = run; run += h3;
    unsigned o2 = run; run += h2;
    unsigned o1 = run; run += h1;
    unsigned o0 = run; run += h0;
    g_off[base + t*4 + 0] = o0;
    g_off[base + t*4 + 1] = o1;
    g_off[base + t*4 + 2] = o2;
    g_off[base + t*4 + 3] = o3;
    if (t == 0) b_chunk[blockIdx.x] = run;       // chunk total

    if (t == 0) {
        __threadfence();
        s_last = (atomicAdd(&g_done, 1u) == NCH - 1u) ? 1u : 0u;
    }
    __syncthreads();
    if (s_last) {
        volatile unsigned* vc = (volatile unsigned*)b_chunk;
        if (t < NCH) {
            unsigned suf = 0;
            for (int i = t + 1; i < NCH; i++) suf += vc[i];
            b_csuf[t] = suf;
            if (t == 0) {
                unsigned tot = suf + vc[0];
                g_tot_raw = tot;
                g_total = min(tot, (unsigned)KPK);
                g_done = 0u;                     // reset ticket for next replay
            }
        }
    }
}

// ---- kernel 4: scatter payloads into rank position + write padding rows -------
// Threads [0, CAND_CAP): rank assignment via atomicAdd(-1) — this also restores
// g_hist to all-zeros. Threads [CAND_CAP, CAND_CAP+KPK): zero the padding rows
// of the output (rows >= g_total) directly.
__global__ void k_scatter(float* __restrict__ out, float* __restrict__ validOut,
                          int writeValid) {
    unsigned i = blockIdx.x * blockDim.x + threadIdx.x;
    if (i < (unsigned)CAND_CAP) {
        unsigned n = min(g_ncand, (unsigned)CAND_CAP);
        if (i >= n) return;
        unsigned b = g_cand_bucket[i];
        if (b == INVALID_B) return;
        unsigned old = atomicAdd(&g_hist[b], 0xFFFFFFFFu);    // cnt..1; ends at 0
        unsigned pos = g_off[b] + b_csuf[b >> 10] + old - 1u;
        if (pos < (unsigned)KPK) {
            g_sidx[pos] = g_cand[i].x;
            g_spay[pos] = g_pay[i];
        }
    } else {
        unsigned row = i - (unsigned)CAND_CAP;
        if (row < (unsigned)KPK && row >= g_total) {
            ((float4*)out)[row] = make_float4(0.f, 0.f, 0.f, 0.f);
            if (writeValid) validOut[row] = 0.f;
        }
    }
}

// ---- kernel 5: per-bucket index sort (ties: lower index first) + final write --
// One thread per value bucket: sorts its records by voxel index (ascending; this
// exactly reproduces lax.top_k's stable tie-break among identical values) and
// writes the final output rows. Also restores cell/compact counters for replay.
__global__ void k_finalize(float* __restrict__ out, float* __restrict__ validOut,
                           int writeValid) {
    unsigned b = blockIdx.x * blockDim.x + threadIdx.x;
    if (b >= NB) return;
    c_cnt[b] = 0u;                               // restore cell counters
    if (b == 0u) g_ncand = 0u;                   // restore compact counter
    unsigned F = g_off[b] + b_csuf[b >> 10];
    unsigned Fprev = (b == 0u) ? g_tot_raw : (g_off[b - 1] + b_csuf[(b - 1) >> 10]);
    unsigned c = Fprev - F;                      // bucket count recovered from scan
    if (c == 0u) return;
    if (F >= (unsigned)KPK) return;
    if (F + c > (unsigned)KPK) c = (unsigned)KPK - F;

    if (c == 1u) {
        ((float4*)out)[F] = g_spay[F];
        if (writeValid) validOut[F] = 1.f;
        return;
    }
    if (c <= (unsigned)LOCAL_SORT) {
        unsigned idxv[LOCAL_SORT];
        unsigned ord[LOCAL_SORT];
        for (unsigned j = 0; j < c; j++) { idxv[j] = g_sidx[F + j]; ord[j] = j; }
        for (unsigned ii = 1; ii < c; ii++) {
            unsigned kv = idxv[ii], ko = ord[ii];
            int j = (int)ii - 1;
            while (j >= 0 && idxv[j] > kv) {
                idxv[j + 1] = idxv[j]; ord[j + 1] = ord[j]; j--;
            }
            idxv[j + 1] = kv; ord[j + 1] = ko;
        }
        for (unsigned r = 0; r < c; r++) {
            ((float4*)out)[F + r] = g_spay[F + ord[r]];
            if (writeValid) validOut[F + r] = 1.f;
        }
    } else {
        // fallback (astronomically rare): in-place dual-array insertion sort
        for (unsigned ii = 1; ii < c; ii++) {
            unsigned key = g_sidx[F + ii];
            float4 pay = g_spay[F + ii];
            int j = (int)ii - 1;
            while (j >= 0 && g_sidx[F + j] > key) {
                g_sidx[F + j + 1] = g_sidx[F + j];
                g_spay[F + j + 1] = g_spay[F + j];
                j--;
            }
            g_sidx[F + j + 1] = key;
            g_spay[F + j + 1] = pay;
        }
        for (unsigned r = 0; r < c; r++) {
            ((float4*)out)[F + r] = g_spay[F + r];
            if (writeValid) validOut[F + r] = 1.f;
        }
    }
}

// ---------------- launch (5 kernels) ----------------
extern "C" void kernel_launch(void* const* d_in, const int* in_sizes, int n_in,
                              void* d_out, int out_size) {
    const float* vol = (const float*)d_in[0];
    float* out = (float*)d_out;
    int writeValid = (out_size >= KPK * 5) ? 1 : 0;
    float* validOut = out + (size_t)KPK * 4;

    k_detect<<<4096, 256>>>(vol);
    k_verify_cent<<<CAND_CAP / 256, 256>>>(vol);
    k_scan<<<NCH, 256>>>();
    k_scatter<<<(CAND_CAP + KPK) / 256, 256>>>(out, validOut, writeValid);
    k_finalize<<<NB / 256, 256>>>(out, validOut, writeValid);
}

// round 12
// speedup vs baseline: 1.0049x; 1.0049x over previous
#include <cuda_runtime.h>
#include <cuda_bf16.h>

#define DD 128
#define HH 512
#define WW 512
#define THRESH 0.997f
#define KPK 131072
#define NB  65536                 // value buckets AND spatial cells (16*64*64)
#define NCH 64                    // scan chunks of 1024 buckets
#define CSLOTS 16                 // per-cell candidate capacity (lambda~1.5 -> safe)
#define BSLOTS 16                 // per-bucket peak capacity (lambda~1.1 -> safe)
#define CAND_CAP (1<<18)          // 262144

// ------------- device scratch (static; all counters self-restore to 0) --------
__device__ unsigned c_cnt[NB];                // per-cell count   (zeroed by finalize)
__device__ uint2    c_data[NB * CSLOTS];      // (idx, valbits) per cell slot
__device__ unsigned g_ncand;                  // compact count    (zeroed by finalize)
__device__ uint2    g_cand[CAND_CAP];         // compact candidate list (idx, valbits)
__device__ unsigned g_hist[NB];               // per-bucket peak count (zeroed by finalize)
__device__ unsigned b_sidx[NB * BSLOTS];      // voxel idx per bucket slot
__device__ float4   b_pay [NB * BSLOTS];      // output payload per bucket slot
__device__ unsigned g_off[NB];                // within-chunk strictly-after offsets
__device__ unsigned b_chunk[NCH];
__device__ unsigned b_csuf[NCH];
__device__ unsigned g_done;                   // scan ticket (reset by last block)
__device__ unsigned g_total;                  // min(raw, KPK)

__device__ __forceinline__ unsigned cell_of(unsigned idx) {
    unsigned z = idx >> 18, y = (idx >> 9) & 511u, x = idx & 511u;
    return ((z >> 3) << 12) | ((y >> 3) << 6) | (x >> 3);
}

// ---- kernel 1: stream volume; block-aggregated compact append + cell slots ----
__global__ void k_detect(const float* __restrict__ vol) {
    __shared__ uint2 s_cand[1024];
    __shared__ unsigned s_cnt, s_base;
    if (threadIdx.x == 0) s_cnt = 0u;
    __syncthreads();

    const float4* v4 = (const float4*)vol;
    unsigned tile = blockIdx.x * 2048u;
#pragma unroll
    for (int j = 0; j < 8; j++) {
        unsigned i = tile + j * 256u + threadIdx.x;
        float4 f = v4[i];
        unsigned base = i * 4u;
        float vv[4] = {f.x, f.y, f.z, f.w};
#pragma unroll
        for (int e = 0; e < 4; e++) {
            if (vv[e] > THRESH) {
                unsigned p = atomicAdd(&s_cnt, 1u);
                if (p < 1024u) s_cand[p] = make_uint2(base + (unsigned)e, __float_as_uint(vv[e]));
            }
        }
    }
    __syncthreads();
    unsigned cnt = min(s_cnt, 1024u);
    if (threadIdx.x == 0) s_base = atomicAdd(&g_ncand, cnt);
    __syncthreads();
    for (unsigned j = threadIdx.x; j < cnt; j += blockDim.x) {
        uint2 rec = s_cand[j];
        unsigned p = s_base + j;
        if (p < CAND_CAP) g_cand[p] = rec;
        unsigned c = cell_of(rec.x);
        unsigned slot = atomicAdd(&c_cnt[c], 1u);   // 65536 addrs: no contention
        if (slot < CSLOTS) c_data[c * CSLOTS + slot] = rec;
    }
}

// ---- kernel 2: verify 7^3 local max via cell probes; peaks -> bucket slots ----
// A defeating neighbor (> v > 0.997) is itself a candidate, so only candidate
// records in the <=8 overlapping cells need checking. Surviving peaks get the
// full centroid + reconstruction here (order-independent) and are deposited
// directly into their value-bucket's slot array (one atomic = slot + histogram).
__global__ void k_verify_cent(const float* __restrict__ vol) {
    unsigned i = blockIdx.x * blockDim.x + threadIdx.x;
    unsigned n = min(g_ncand, (unsigned)CAND_CAP);
    if (i >= n) return;
    uint2 me = g_cand[i];
    unsigned idx = me.x;
    float v = __uint_as_float(me.y);
    int z = idx >> 18, y = (idx >> 9) & 511, x = idx & 511;

    int cz0 = max(z - 3, 0) >> 3, cz1 = min(z + 3, DD - 1) >> 3;
    int cy0 = max(y - 3, 0) >> 3, cy1 = min(y + 3, HH - 1) >> 3;
    int cx0 = max(x - 3, 0) >> 3, cx1 = min(x + 3, WW - 1) >> 3;
    bool peak = true;
    for (int cz = cz0; cz <= cz1 && peak; cz++)
    for (int cy = cy0; cy <= cy1 && peak; cy++)
    for (int cx = cx0; cx <= cx1 && peak; cx++) {
        unsigned c2 = ((unsigned)cz << 12) | ((unsigned)cy << 6) | (unsigned)cx;
        unsigned cn2 = min(c_cnt[c2], (unsigned)CSLOTS);
        unsigned b2 = c2 * CSLOTS;
        for (unsigned j = 0; j < cn2; j++) {
            uint2 r = c_data[b2 + j];
            if (__uint_as_float(r.y) > v) {
                int rz = r.x >> 18, ry = (r.x >> 9) & 511, rx = r.x & 511;
                if (abs(rz - z) <= 3 && abs(ry - y) <= 3 && abs(rx - x) <= 3) {
                    peak = false; break;
                }
            }
        }
    }
    if (!peak) return;

    // centroid over the 7^3 patch: each x-run covered by three aligned float4
    // loads from a = clamp((x-3)&~3, 0, 500), out-of-window weight-masked
    // (matches the reference's zero padding).
    int a = max(x - 3, 0) & ~3;
    if (a > WW - 12) a = WW - 12;
    float s0 = 0.f, sx = 0.f, sy = 0.f, sz = 0.f;
#pragma unroll
    for (int dz = -3; dz <= 3; dz++) {
        int zz = z + dz;
        if ((unsigned)zz >= (unsigned)DD) continue;
        const float* pz = vol + ((unsigned)zz << 18);
#pragma unroll
        for (int dy = -3; dy <= 3; dy++) {
            int yy = y + dy;
            if ((unsigned)yy >= (unsigned)HH) continue;
            const float* rp = pz + ((unsigned)yy << 9);
            float4 A = *(const float4*)(rp + a);
            float4 B = *(const float4*)(rp + a + 4);
            float4 C = *(const float4*)(rp + a + 8);
            float vals[12] = {A.x, A.y, A.z, A.w, B.x, B.y, B.z, B.w, C.x, C.y, C.z, C.w};
            float rs0 = 0.f, rsx = 0.f;
#pragma unroll
            for (int e = 0; e < 12; e++) {
                int dx = a + e - x;
                bool in = (dx >= -3) && (dx <= 3);
                float vv = in ? vals[e] : 0.f;
                rs0 += vv;
                rsx += vv * (float)dx;
            }
            s0 += rs0;
            sx += rsx;
            sy += rs0 * (float)dy;
            sz += rs0 * (float)dz;
        }
    }
    float inv  = 1.f / s0;
    float xrec = ((float)x + sx * inv - 255.5f) * 0.1f;
    float yrec = ((float)y + sy * inv - 255.5f) * 0.1f;
    float zrec = ((float)z + sz * inv + 0.5f) * 0.02f - 2.0f;

    // deposit into value-bucket slot (bucket index <-> exact float value,
    // since all peaks share the top 16 bits 0x3F7F)
    unsigned bucket = me.y & 0xFFFFu;
    unsigned slot = atomicAdd(&g_hist[bucket], 1u);
    if (slot < BSLOTS) {
        b_sidx[bucket * BSLOTS + slot] = idx;
        b_pay [bucket * BSLOTS + slot] = make_float4(xrec, yrec, zrec, v);
    }
}

// ---- kernel 3: fused two-level suffix (descending) scan over 65536 buckets ----
__global__ void k_scan() {
    __shared__ unsigned s_h[1024];
    __shared__ unsigned s_w[8];
    __shared__ unsigned s_last;
    int t = threadIdx.x;
    unsigned base = blockIdx.x * 1024u;
#pragma unroll
    for (int j = 0; j < 4; j++) s_h[j * 256 + t] = g_hist[base + j * 256 + t];
    __syncthreads();
    unsigned h0 = s_h[t*4+0], h1 = s_h[t*4+1], h2 = s_h[t*4+2], h3 = s_h[t*4+3];
    unsigned sum4 = h0 + h1 + h2 + h3;
    unsigned v = sum4;
    int lane = t & 31, w = t >> 5;
#pragma unroll
    for (int d = 1; d < 32; d <<= 1) {
        unsigned o = __shfl_down_sync(0xFFFFFFFFu, v, d);
        if (lane + d < 32) v += o;
    }
    if (lane == 0) s_w[w] = v;
    __syncthreads();
    unsigned wafter = 0;
    for (int i = w + 1; i < 8; i++) wafter += s_w[i];
    unsigned run = wafter + (v - sum4);          // strictly-after, within chunk
    unsigned o3 = run; run += h3;
    unsigned o2 = run; run += h2;
    unsigned o1 = run; run += h1;
    unsigned o0 = run; run += h0;
    g_off[base + t*4 + 0] = o0;
    g_off[base + t*4 + 1] = o1;
    g_off[base + t*4 + 2] = o2;
    g_off[base + t*4 + 3] = o3;
    if (t == 0) b_chunk[blockIdx.x] = run;       // chunk total

    if (t == 0) {
        __threadfence();
        s_last = (atomicAdd(&g_done, 1u) == NCH - 1u) ? 1u : 0u;
    }
    __syncthreads();
    if (s_last) {
        volatile unsigned* vc = (volatile unsigned*)b_chunk;
        if (t < NCH) {
            unsigned suf = 0;
            for (int i = t + 1; i < NCH; i++) suf += vc[i];
            b_csuf[t] = suf;
            if (t == 0) {
                g_total = min(suf + vc[0], (unsigned)KPK);
                g_done = 0u;                     // reset ticket for next replay
            }
        }
    }
}

// ---- kernel 4: thread-per-bucket: sort slots by index, write output + padding --
// Bucket index ordering == value ordering (descending via suffix scan); within a
// bucket all values are the identical float, and ascending voxel index exactly
// reproduces lax.top_k's stable tie-break. Also restores all counters to zero.
__global__ void k_finalize(float* __restrict__ out, float* __restrict__ validOut,
                           int writeValid) {
    unsigned b = blockIdx.x * blockDim.x + threadIdx.x;
    if (b >= NB) return;

    unsigned total = g_total;
    // zero-padding rows (row >= total), strided across NB threads
    for (unsigned row = b; row < (unsigned)KPK; row += NB) {
        if (row >= total) {
            ((float4*)out)[row] = make_float4(0.f, 0.f, 0.f, 0.f);
            if (writeValid) validOut[row] = 0.f;
        }
    }

    // counter restoration for graph replay
    c_cnt[b] = 0u;
    if (b == 0u) g_ncand = 0u;

    unsigned c = g_hist[b];
    g_hist[b] = 0u;
    if (c == 0u) return;
    if (c > (unsigned)BSLOTS) c = (unsigned)BSLOTS;   // P ~ 1e-13
    unsigned F = g_off[b] + b_csuf[b >> 10];
    if (F >= (unsigned)KPK) return;
    if (F + c > (unsigned)KPK) c = (unsigned)KPK - F;

    unsigned s = b * BSLOTS;
    if (c == 1u) {
        ((float4*)out)[F] = b_pay[s];
        if (writeValid) validOut[F] = 1.f;
        return;
    }
    unsigned idxv[BSLOTS];
    unsigned ord[BSLOTS];
    for (unsigned j = 0; j < c; j++) { idxv[j] = b_sidx[s + j]; ord[j] = j; }
    for (unsigned ii = 1; ii < c; ii++) {
        unsigned kv = idxv[ii], ko = ord[ii];
        int j = (int)ii - 1;
        while (j >= 0 && idxv[j] > kv) {
            idxv[j + 1] = idxv[j]; ord[j + 1] = ord[j]; j--;
        }
        idxv[j + 1] = kv; ord[j + 1] = ko;
    }
    for (unsigned r = 0; r < c; r++) {
        ((float4*)out)[F + r] = b_pay[s + ord[r]];
        if (writeValid) validOut[F + r] = 1.f;
    }
}

// ---------------- launch (4 kernels) ----------------
extern "C" void kernel_launch(void* const* d_in, const int* in_sizes, int n_in,
                              void* d_out, int out_size) {
    const float* vol = (const float*)d_in[0];
    float* out = (float*)d_out;
    int writeValid = (out_size >= KPK * 5) ? 1 : 0;
    float* validOut = out + (size_t)KPK * 4;

    k_detect<<<4096, 256>>>(vol);
    k_verify_cent<<<CAND_CAP / 256, 256>>>(vol);
    k_scan<<<NCH, 256>>>();
    k_finalize<<<NB / 256, 256>>>(out, validOut, writeValid);
}

// round 13
// speedup vs baseline: 1.0114x; 1.0065x over previous
#include <cuda_runtime.h>
#include <cuda_bf16.h>

#define DD 128
#define HH 512
#define WW 512
#define THRESH 0.997f
#define KPK 131072
#define NB  65536                 // value buckets AND spatial cells (16*64*64)
#define NCH 64                    // scan chunks of 1024 buckets
#define CSLOTS 16                 // per-cell candidate capacity (lambda~1.5 -> safe)
#define BSLOTS 16                 // per-bucket peak capacity (lambda~1.1 -> safe)
#define CAND_CAP (1<<18)          // 262144

// ------------- device scratch (static; all counters self-restore to 0) --------
__device__ unsigned c_cnt[NB];                // per-cell count   (zeroed by finalize)
__device__ uint2    c_data[NB * CSLOTS];      // (idx, valbits) per cell slot
__device__ unsigned g_ncand;                  // compact count    (zeroed by finalize)
__device__ uint2    g_cand[CAND_CAP];         // compact candidate list (idx, valbits)
__device__ unsigned g_hist[NB];               // per-bucket peak count (zeroed by finalize)
__device__ unsigned b_sidx[NB * BSLOTS];      // voxel idx per bucket slot
__device__ float4   b_pay [NB * BSLOTS];      // output payload per bucket slot
__device__ unsigned g_off[NB];                // within-chunk strictly-after offsets
__device__ unsigned b_chunk[NCH];
__device__ unsigned b_csuf[NCH];
__device__ unsigned g_done;                   // scan ticket (reset by last block)
__device__ unsigned g_total;                  // min(raw, KPK)

__device__ __forceinline__ unsigned cell_of(unsigned idx) {
    unsigned z = idx >> 18, y = (idx >> 9) & 511u, x = idx & 511u;
    return ((z >> 3) << 12) | ((y >> 3) << 6) | (x >> 3);
}

// ---- kernel 1: stream volume; block-aggregated compact append + cell slots ----
__global__ void k_detect(const float* __restrict__ vol) {
    __shared__ uint2 s_cand[1024];
    __shared__ unsigned s_cnt, s_base;
    if (threadIdx.x == 0) s_cnt = 0u;
    __syncthreads();

    const float4* v4 = (const float4*)vol;
    unsigned tile = blockIdx.x * 2048u;
#pragma unroll
    for (int j = 0; j < 8; j++) {
        unsigned i = tile + j * 256u + threadIdx.x;
        float4 f = v4[i];
        unsigned base = i * 4u;
        float vv[4] = {f.x, f.y, f.z, f.w};
#pragma unroll
        for (int e = 0; e < 4; e++) {
            if (vv[e] > THRESH) {
                unsigned p = atomicAdd(&s_cnt, 1u);
                if (p < 1024u) s_cand[p] = make_uint2(base + (unsigned)e, __float_as_uint(vv[e]));
            }
        }
    }
    __syncthreads();
    unsigned cnt = min(s_cnt, 1024u);
    if (threadIdx.x == 0) s_base = atomicAdd(&g_ncand, cnt);
    __syncthreads();
    for (unsigned j = threadIdx.x; j < cnt; j += blockDim.x) {
        uint2 rec = s_cand[j];
        unsigned p = s_base + j;
        if (p < CAND_CAP) g_cand[p] = rec;
        unsigned c = cell_of(rec.x);
        unsigned slot = atomicAdd(&c_cnt[c], 1u);   // 65536 addrs: no contention
        if (slot < CSLOTS) c_data[c * CSLOTS + slot] = rec;
    }
}

// ---- kernel 2: verify 7^3 local max via cell probes; peaks -> bucket slots ----
// A defeating neighbor (> v > 0.997) is itself a candidate, so only candidate
// records in the <=8 overlapping cells need checking. Surviving peaks get the
// full centroid + reconstruction here (order-independent) and are deposited
// directly into their value-bucket's slot array (one atomic = slot + histogram).
__global__ void k_verify_cent(const float* __restrict__ vol) {
    unsigned i = blockIdx.x * blockDim.x + threadIdx.x;
    unsigned n = min(g_ncand, (unsigned)CAND_CAP);
    if (i >= n) return;
    uint2 me = g_cand[i];
    unsigned idx = me.x;
    float v = __uint_as_float(me.y);
    int z = idx >> 18, y = (idx >> 9) & 511, x = idx & 511;

    int cz0 = max(z - 3, 0) >> 3, cz1 = min(z + 3, DD - 1) >> 3;
    int cy0 = max(y - 3, 0) >> 3, cy1 = min(y + 3, HH - 1) >> 3;
    int cx0 = max(x - 3, 0) >> 3, cx1 = min(x + 3, WW - 1) >> 3;
    bool peak = true;
    for (int cz = cz0; cz <= cz1 && peak; cz++)
    for (int cy = cy0; cy <= cy1 && peak; cy++)
    for (int cx = cx0; cx <= cx1 && peak; cx++) {
        unsigned c2 = ((unsigned)cz << 12) | ((unsigned)cy << 6) | (unsigned)cx;
        unsigned cn2 = min(c_cnt[c2], (unsigned)CSLOTS);
        unsigned b2 = c2 * CSLOTS;
        for (unsigned j = 0; j < cn2; j++) {
            uint2 r = c_data[b2 + j];
            if (__uint_as_float(r.y) > v) {
                int rz = r.x >> 18, ry = (r.x >> 9) & 511, rx = r.x & 511;
                if (abs(rz - z) <= 3 && abs(ry - y) <= 3 && abs(rx - x) <= 3) {
                    peak = false; break;
                }
            }
        }
    }
    if (!peak) return;

    // centroid over the 7^3 patch: each x-run covered by three aligned float4
    // loads from a = clamp((x-3)&~3, 0, 500), out-of-window weight-masked
    // (matches the reference's zero padding).
    int a = max(x - 3, 0) & ~3;
    if (a > WW - 12) a = WW - 12;
    float s0 = 0.f, sx = 0.f, sy = 0.f, sz = 0.f;
#pragma unroll
    for (int dz = -3; dz <= 3; dz++) {
        int zz = z + dz;
        if ((unsigned)zz >= (unsigned)DD) continue;
        const float* pz = vol + ((unsigned)zz << 18);
#pragma unroll
        for (int dy = -3; dy <= 3; dy++) {
            int yy = y + dy;
            if ((unsigned)yy >= (unsigned)HH) continue;
            const float* rp = pz + ((unsigned)yy << 9);
            float4 A = *(const float4*)(rp + a);
            float4 B = *(const float4*)(rp + a + 4);
            float4 C = *(const float4*)(rp + a + 8);
            float vals[12] = {A.x, A.y, A.z, A.w, B.x, B.y, B.z, B.w, C.x, C.y, C.z, C.w};
            float rs0 = 0.f, rsx = 0.f;
#pragma unroll
            for (int e = 0; e < 12; e++) {
                int dx = a + e - x;
                bool in = (dx >= -3) && (dx <= 3);
                float vv = in ? vals[e] : 0.f;
                rs0 += vv;
                rsx += vv * (float)dx;
            }
            s0 += rs0;
            sx += rsx;
            sy += rs0 * (float)dy;
            sz += rs0 * (float)dz;
        }
    }
    float inv  = 1.f / s0;
    float xrec = ((float)x + sx * inv - 255.5f) * 0.1f;
    float yrec = ((float)y + sy * inv - 255.5f) * 0.1f;
    float zrec = ((float)z + sz * inv + 0.5f) * 0.02f - 2.0f;

    // deposit into value-bucket slot (bucket index <-> exact float value,
    // since all peaks share the top 16 bits 0x3F7F)
    unsigned bucket = me.y & 0xFFFFu;
    unsigned slot = atomicAdd(&g_hist[bucket], 1u);
    if (slot < BSLOTS) {
        b_sidx[bucket * BSLOTS + slot] = idx;
        b_pay [bucket * BSLOTS + slot] = make_float4(xrec, yrec, zrec, v);
    }
}

// ---- kernel 3: fused two-level suffix (descending) scan over 65536 buckets ----
__global__ void k_scan() {
    __shared__ unsigned s_h[1024];
    __shared__ unsigned s_w[8];
    __shared__ unsigned s_last;
    int t = threadIdx.x;
    unsigned base = blockIdx.x * 1024u;
#pragma unroll
    for (int j = 0; j < 4; j++) s_h[j * 256 + t] = g_hist[base + j * 256 + t];
    __syncthreads();
    unsigned h0 = s_h[t*4+0], h1 = s_h[t*4+1], h2 = s_h[t*4+2], h3 = s_h[t*4+3];
    unsigned sum4 = h0 + h1 + h2 + h3;
    unsigned v = sum4;
    int lane = t & 31, w = t >> 5;
#pragma unroll
    for (int d = 1; d < 32; d <<= 1) {
        unsigned o = __shfl_down_sync(0xFFFFFFFFu, v, d);
        if (lane + d < 32) v += o;
    }
    if (lane == 0) s_w[w] = v;
    __syncthreads();
    unsigned wafter = 0;
    for (int i = w + 1; i < 8; i++) wafter += s_w[i];
    unsigned run = wafter + (v - sum4);          // strictly-after, within chunk
    unsigned o3 = run; run += h3;
    unsigned o2 = run; run += h2;
    unsigned o1 = run; run += h1;
    unsigned o0 = run; run += h0;
    g_off[base + t*4 + 0] = o0;
    g_off[base + t*4 + 1] = o1;
    g_off[base + t*4 + 2] = o2;
    g_off[base + t*4 + 3] = o3;
    if (t == 0) b_chunk[blockIdx.x] = run;       // chunk total

    if (t == 0) {
        __threadfence();
        s_last = (atomicAdd(&g_done, 1u) == NCH - 1u) ? 1u : 0u;
    }
    __syncthreads();
    if (s_last) {
        volatile unsigned* vc = (volatile unsigned*)b_chunk;
        if (t < NCH) {
            unsigned suf = 0;
            for (int i = t + 1; i < NCH; i++) suf += vc[i];
            b_csuf[t] = suf;
            if (t == 0) {
                g_total = min(suf + vc[0], (unsigned)KPK);
                g_done = 0u;                     // reset ticket for next replay
            }
        }
    }
}

// ---- kernel 4: thread-per-bucket finalize, MLP-batched ------------------------
// All loads a thread might need for the dominant c<=4 case are issued
// unconditionally and independently BEFORE any data-dependent branch:
// hist, off, csuf, slots 0-3 of sidx (one uint4), and payload 0. This turns a
// ~5-deep dependent chain into ~1-2 latency rounds (kernel is latency-bound:
// only 2048 warps chip-wide). Bucket index ordering == value ordering; within a
// bucket ascending voxel index reproduces lax.top_k's stable tie-break.
__global__ void k_finalize(float* __restrict__ out, float* __restrict__ validOut,
                           int writeValid) {
    unsigned b = blockIdx.x * blockDim.x + threadIdx.x;
    if (b >= NB) return;

    // --- issue every potentially-needed load up front (independent; MLP~6) ---
    unsigned craw = g_hist[b];
    unsigned off  = g_off[b];
    unsigned csuf = b_csuf[b >> 10];
    uint4  s4 = *((const uint4*)(b_sidx + b * BSLOTS));   // slots 0..3
    float4 p0 = b_pay[b * BSLOTS + 0];
    unsigned total = g_total;

    // padding rows (row >= total), strided across NB threads — independent writes
#pragma unroll
    for (unsigned k = 0; k < KPK / NB; k++) {
        unsigned row = b + k * NB;
        if (row >= total) {
            ((float4*)out)[row] = make_float4(0.f, 0.f, 0.f, 0.f);
            if (writeValid) validOut[row] = 0.f;
        }
    }
    // counter restoration for graph replay — independent stores
    c_cnt[b] = 0u;
    if (craw != 0u) g_hist[b] = 0u;
    if (b == 0u) g_ncand = 0u;

    if (craw == 0u) return;
    unsigned c = min(craw, (unsigned)BSLOTS);
    unsigned F = off + csuf;
    if (F >= (unsigned)KPK) return;
    if (F + c > (unsigned)KPK) c = (unsigned)KPK - F;

    if (c == 1u) {                                   // ~75% of occupied buckets
        ((float4*)out)[F] = p0;
        if (writeValid) validOut[F] = 1.f;
        return;
    }

    unsigned s = b * BSLOTS;
    if (c <= 4u) {                                   // ~24%: one more load round
        float4 pay[4];
        pay[0] = p0;
        for (unsigned j = 1; j < c; j++) pay[j] = b_pay[s + j];
        unsigned idxv[4] = {s4.x, s4.y, s4.z, s4.w};
        unsigned ord[4]  = {0u, 1u, 2u, 3u};
        for (unsigned ii = 1; ii < c; ii++) {
            unsigned kv = idxv[ii], ko = ord[ii];
            int j = (int)ii - 1;
            while (j >= 0 && idxv[j] > kv) {
                idxv[j + 1] = idxv[j]; ord[j + 1] = ord[j]; j--;
            }
            idxv[j + 1] = kv; ord[j + 1] = ko;
        }
        for (unsigned r = 0; r < c; r++) {
            ((float4*)out)[F + r] = pay[ord[r]];
            if (writeValid) validOut[F + r] = 1.f;
        }
        return;
    }

    // rare tail (<1% of buckets): full-width sort
    unsigned idxv[BSLOTS];
    unsigned ord[BSLOTS];
    idxv[0] = s4.x; idxv[1] = s4.y; idxv[2] = s4.z; idxv[3] = s4.w;
    for (unsigned j = 4; j < c; j++) idxv[j] = b_sidx[s + j];
    for (unsigned j = 0; j < c; j++) ord[j] = j;
    for (unsigned ii = 1; ii < c; ii++) {
        unsigned kv = idxv[ii], ko = ord[ii];
        int j = (int)ii - 1;
        while (j >= 0 && idxv[j] > kv) {
            idxv[j + 1] = idxv[j]; ord[j + 1] = ord[j]; j--;
        }
        idxv[j + 1] = kv; ord[j + 1] = ko;
    }
    for (unsigned r = 0; r < c; r++) {
        ((float4*)out)[F + r] = b_pay[s + ord[r]];
        if (writeValid) validOut[F + r] = 1.f;
    }
}

// ---------------- launch (4 kernels) ----------------
extern "C" void kernel_launch(void* const* d_in, const int* in_sizes, int n_in,
                              void* d_out, int out_size) {
    const float* vol = (const float*)d_in[0];
    float* out = (float*)d_out;
    int writeValid = (out_size >= KPK * 5) ? 1 : 0;
    float* validOut = out + (size_t)KPK * 4;

    k_detect<<<4096, 256>>>(vol);
    k_verify_cent<<<CAND_CAP / 256, 256>>>(vol);
    k_scan<<<NCH, 256>>>();
    k_finalize<<<NB / 256, 256>>>(out, validOut, writeValid);
}

// round 14
// speedup vs baseline: 1.0177x; 1.0062x over previous
#include <cuda_runtime.h>
#include <cuda_bf16.h>

#define DD 128
#define HH 512
#define WW 512
#define THRESH 0.997f
#define KPK 131072
#define NB  65536                 // value buckets AND spatial cells (16*64*64)
#define NCH 64                    // scan chunks of 1024 buckets
#define CSLOTS 16                 // per-cell candidate capacity (lambda~1.5 -> safe)
#define BSLOTS 16                 // per-bucket peak capacity (lambda~1.1 -> safe)
#define CAND_CAP (1<<18)          // 262144
#define NBLK_BUCKET (NB / 256)    // 256
#define NBLK_PAD    (KPK / 256)   // 512

// ------------- device scratch (static; all counters self-restore to 0) --------
__device__ unsigned c_cnt[NB];                // per-cell count   (zeroed by finalize)
__device__ uint2    c_data[NB * CSLOTS];      // (idx, valbits) per cell slot
__device__ unsigned g_ncand;                  // compact count    (zeroed by finalize)
__device__ uint2    g_cand[CAND_CAP];         // compact candidate list (idx, valbits)
__device__ unsigned g_hist[NB];               // per-bucket peak count (zeroed by finalize)
__device__ unsigned b_sidx[NB * BSLOTS];      // voxel idx per bucket slot
__device__ float4   b_pay [NB * BSLOTS];      // output payload per bucket slot
__device__ unsigned g_off[NB];                // within-chunk strictly-after offsets
__device__ unsigned b_chunk[NCH];
__device__ unsigned b_csuf[NCH];
__device__ unsigned g_done;                   // scan ticket (reset by last block)
__device__ unsigned g_total;                  // min(raw, KPK)

__device__ __forceinline__ unsigned cell_of(unsigned idx) {
    unsigned z = idx >> 18, y = (idx >> 9) & 511u, x = idx & 511u;
    return ((z >> 3) << 12) | ((y >> 3) << 6) | (x >> 3);
}

// ---- kernel 1: stream volume; block-aggregated compact append + cell slots ----
__global__ void k_detect(const float* __restrict__ vol) {
    __shared__ uint2 s_cand[1024];
    __shared__ unsigned s_cnt, s_base;
    if (threadIdx.x == 0) s_cnt = 0u;
    __syncthreads();

    const float4* v4 = (const float4*)vol;
    unsigned tile = blockIdx.x * 2048u;
#pragma unroll
    for (int j = 0; j < 8; j++) {
        unsigned i = tile + j * 256u + threadIdx.x;
        float4 f = v4[i];
        unsigned base = i * 4u;
        float vv[4] = {f.x, f.y, f.z, f.w};
#pragma unroll
        for (int e = 0; e < 4; e++) {
            if (vv[e] > THRESH) {
                unsigned p = atomicAdd(&s_cnt, 1u);
                if (p < 1024u) s_cand[p] = make_uint2(base + (unsigned)e, __float_as_uint(vv[e]));
            }
        }
    }
    __syncthreads();
    unsigned cnt = min(s_cnt, 1024u);
    if (threadIdx.x == 0) s_base = atomicAdd(&g_ncand, cnt);
    __syncthreads();
    for (unsigned j = threadIdx.x; j < cnt; j += blockDim.x) {
        uint2 rec = s_cand[j];
        unsigned p = s_base + j;
        if (p < CAND_CAP) g_cand[p] = rec;
        unsigned c = cell_of(rec.x);
        unsigned slot = atomicAdd(&c_cnt[c], 1u);   // 65536 addrs: no contention
        if (slot < CSLOTS) c_data[c * CSLOTS + slot] = rec;
    }
}

// ---- kernel 2: verify 7^3 local max via cell probes; peaks -> bucket slots ----
// A defeating neighbor (> v > 0.997) is itself a candidate, so only candidate
// records in the <=8 overlapping cells need checking. Surviving peaks get the
// full centroid + reconstruction here (order-independent) and are deposited
// directly into their value-bucket's slot array (one atomic = slot + histogram).
__global__ void k_verify_cent(const float* __restrict__ vol) {
    unsigned i = blockIdx.x * blockDim.x + threadIdx.x;
    unsigned n = min(g_ncand, (unsigned)CAND_CAP);
    if (i >= n) return;
    uint2 me = g_cand[i];
    unsigned idx = me.x;
    float v = __uint_as_float(me.y);
    int z = idx >> 18, y = (idx >> 9) & 511, x = idx & 511;

    int cz0 = max(z - 3, 0) >> 3, cz1 = min(z + 3, DD - 1) >> 3;
    int cy0 = max(y - 3, 0) >> 3, cy1 = min(y + 3, HH - 1) >> 3;
    int cx0 = max(x - 3, 0) >> 3, cx1 = min(x + 3, WW - 1) >> 3;
    bool peak = true;
    for (int cz = cz0; cz <= cz1 && peak; cz++)
    for (int cy = cy0; cy <= cy1 && peak; cy++)
    for (int cx = cx0; cx <= cx1 && peak; cx++) {
        unsigned c2 = ((unsigned)cz << 12) | ((unsigned)cy << 6) | (unsigned)cx;
        unsigned cn2 = min(c_cnt[c2], (unsigned)CSLOTS);
        unsigned b2 = c2 * CSLOTS;
        for (unsigned j = 0; j < cn2; j++) {
            uint2 r = c_data[b2 + j];
            if (__uint_as_float(r.y) > v) {
                int rz = r.x >> 18, ry = (r.x >> 9) & 511, rx = r.x & 511;
                if (abs(rz - z) <= 3 && abs(ry - y) <= 3 && abs(rx - x) <= 3) {
                    peak = false; break;
                }
            }
        }
    }
    if (!peak) return;

    // centroid over the 7^3 patch: each x-run covered by three aligned float4
    // loads from a = clamp((x-3)&~3, 0, 500), out-of-window weight-masked
    // (matches the reference's zero padding).
    int a = max(x - 3, 0) & ~3;
    if (a > WW - 12) a = WW - 12;
    float s0 = 0.f, sx = 0.f, sy = 0.f, sz = 0.f;
#pragma unroll
    for (int dz = -3; dz <= 3; dz++) {
        int zz = z + dz;
        if ((unsigned)zz >= (unsigned)DD) continue;
        const float* pz = vol + ((unsigned)zz << 18);
#pragma unroll
        for (int dy = -3; dy <= 3; dy++) {
            int yy = y + dy;
            if ((unsigned)yy >= (unsigned)HH) continue;
            const float* rp = pz + ((unsigned)yy << 9);
            float4 A = *(const float4*)(rp + a);
            float4 B = *(const float4*)(rp + a + 4);
            float4 C = *(const float4*)(rp + a + 8);
            float vals[12] = {A.x, A.y, A.z, A.w, B.x, B.y, B.z, B.w, C.x, C.y, C.z, C.w};
            float rs0 = 0.f, rsx = 0.f;
#pragma unroll
            for (int e = 0; e < 12; e++) {
                int dx = a + e - x;
                bool in = (dx >= -3) && (dx <= 3);
                float vv = in ? vals[e] : 0.f;
                rs0 += vv;
                rsx += vv * (float)dx;
            }
            s0 += rs0;
            sx += rsx;
            sy += rs0 * (float)dy;
            sz += rs0 * (float)dz;
        }
    }
    float inv  = 1.f / s0;
    float xrec = ((float)x + sx * inv - 255.5f) * 0.1f;
    float yrec = ((float)y + sy * inv - 255.5f) * 0.1f;
    float zrec = ((float)z + sz * inv + 0.5f) * 0.02f - 2.0f;

    // deposit into value-bucket slot (bucket index <-> exact float value,
    // since all peaks share the top 16 bits 0x3F7F)
    unsigned bucket = me.y & 0xFFFFu;
    unsigned slot = atomicAdd(&g_hist[bucket], 1u);
    if (slot < BSLOTS) {
        b_sidx[bucket * BSLOTS + slot] = idx;
        b_pay [bucket * BSLOTS + slot] = make_float4(xrec, yrec, zrec, v);
    }
}

// ---- kernel 3: fused two-level suffix (descending) scan over 65536 buckets ----
__global__ void k_scan() {
    __shared__ unsigned s_h[1024];
    __shared__ unsigned s_w[8];
    __shared__ unsigned s_last;
    int t = threadIdx.x;
    unsigned base = blockIdx.x * 1024u;
#pragma unroll
    for (int j = 0; j < 4; j++) s_h[j * 256 + t] = g_hist[base + j * 256 + t];
    __syncthreads();
    unsigned h0 = s_h[t*4+0], h1 = s_h[t*4+1], h2 = s_h[t*4+2], h3 = s_h[t*4+3];
    unsigned sum4 = h0 + h1 + h2 + h3;
    unsigned v = sum4;
    int lane = t & 31, w = t >> 5;
#pragma unroll
    for (int d = 1; d < 32; d <<= 1) {
        unsigned o = __shfl_down_sync(0xFFFFFFFFu, v, d);
        if (lane + d < 32) v += o;
    }
    if (lane == 0) s_w[w] = v;
    __syncthreads();
    unsigned wafter = 0;
    for (int i = w + 1; i < 8; i++) wafter += s_w[i];
    unsigned run = wafter + (v - sum4);          // strictly-after, within chunk
    unsigned o3 = run; run += h3;
    unsigned o2 = run; run += h2;
    unsigned o1 = run; run += h1;
    unsigned o0 = run; run += h0;
    g_off[base + t*4 + 0] = o0;
    g_off[base + t*4 + 1] = o1;
    g_off[base + t*4 + 2] = o2;
    g_off[base + t*4 + 3] = o3;
    if (t == 0) b_chunk[blockIdx.x] = run;       // chunk total

    if (t == 0) {
        __threadfence();
        s_last = (atomicAdd(&g_done, 1u) == NCH - 1u) ? 1u : 0u;
    }
    __syncthreads();
    if (s_last) {
        volatile unsigned* vc = (volatile unsigned*)b_chunk;
        if (t < NCH) {
            unsigned suf = 0;
            for (int i = t + 1; i < NCH; i++) suf += vc[i];
            b_csuf[t] = suf;
            if (t == 0) {
                g_total = min(suf + vc[0], (unsigned)KPK);
                g_done = 0u;                     // reset ticket for next replay
            }
        }
    }
}

// ---- kernel 4: finalize, role-split grid for occupancy ------------------------
// Blocks [0, NBLK_BUCKET): one thread per value bucket — all loads potentially
// needed for the dominant c<=2 case (hist, off, csuf, sidx quad, payloads 0-1)
// issued unconditionally before any branch. Blocks [NBLK_BUCKET, +NBLK_PAD):
// one thread per output row — pure streaming zero-padding for rows >= g_total.
// 6144 warps total vs 2048 before: latency-bound part gets hidden.
__global__ void k_finalize(float* __restrict__ out, float* __restrict__ validOut,
                           int writeValid) {
    if (blockIdx.x >= (unsigned)NBLK_BUCKET) {
        // ---------- padding role: one row per thread ----------
        unsigned row = (blockIdx.x - NBLK_BUCKET) * blockDim.x + threadIdx.x;
        if (row < (unsigned)KPK && row >= g_total) {
            ((float4*)out)[row] = make_float4(0.f, 0.f, 0.f, 0.f);
            if (writeValid) validOut[row] = 0.f;
        }
        return;
    }

    // ---------- bucket role: one bucket per thread ----------
    unsigned b = blockIdx.x * blockDim.x + threadIdx.x;

    // issue every potentially-needed load up front (independent; MLP~7)
    unsigned craw = g_hist[b];
    unsigned off  = g_off[b];
    unsigned csuf = b_csuf[b >> 10];
    uint4  s4 = *((const uint4*)(b_sidx + b * BSLOTS));   // slots 0..3
    float4 p0 = b_pay[b * BSLOTS + 0];
    float4 p1 = b_pay[b * BSLOTS + 1];

    // counter restoration for graph replay — independent stores
    c_cnt[b] = 0u;
    if (craw != 0u) g_hist[b] = 0u;
    if (b == 0u) g_ncand = 0u;

    if (craw == 0u) return;
    unsigned c = min(craw, (unsigned)BSLOTS);
    unsigned F = off + csuf;
    if (F >= (unsigned)KPK) return;
    if (F + c > (unsigned)KPK) c = (unsigned)KPK - F;

    if (c == 1u) {                                   // ~2/3 of occupied buckets
        ((float4*)out)[F] = p0;
        if (writeValid) validOut[F] = 1.f;
        return;
    }
    if (c == 2u) {                                   // most of the rest
        bool sw = s4.x > s4.y;                       // ascending voxel index
        ((float4*)out)[F + 0] = sw ? p1 : p0;
        ((float4*)out)[F + 1] = sw ? p0 : p1;
        if (writeValid) { validOut[F] = 1.f; validOut[F + 1] = 1.f; }
        return;
    }

    unsigned s = b * BSLOTS;
    if (c <= 4u) {
        float4 pay[4];
        pay[0] = p0; pay[1] = p1;
        for (unsigned j = 2; j < c; j++) pay[j] = b_pay[s + j];
        unsigned idxv[4] = {s4.x, s4.y, s4.z, s4.w};
        unsigned ord[4]  = {0u, 1u, 2u, 3u};
        for (unsigned ii = 1; ii < c; ii++) {
            unsigned kv = idxv[ii], ko = ord[ii];
            int j = (int)ii - 1;
            while (j >= 0 && idxv[j] > kv) {
                idxv[j + 1] = idxv[j]; ord[j + 1] = ord[j]; j--;
            }
            idxv[j + 1] = kv; ord[j + 1] = ko;
        }
        for (unsigned r = 0; r < c; r++) {
            ((float4*)out)[F + r] = pay[ord[r]];
            if (writeValid) validOut[F + r] = 1.f;
        }
        return;
    }

    // rare tail (<1% of buckets): full-width sort
    unsigned idxv[BSLOTS];
    unsigned ord[BSLOTS];
    idxv[0] = s4.x; idxv[1] = s4.y; idxv[2] = s4.z; idxv[3] = s4.w;
    for (unsigned j = 4; j < c; j++) idxv[j] = b_sidx[s + j];
    for (unsigned j = 0; j < c; j++) ord[j] = j;
    for (unsigned ii = 1; ii < c; ii++) {
        unsigned kv = idxv[ii], ko = ord[ii];
        int j = (int)ii - 1;
        while (j >= 0 && idxv[j] > kv) {
            idxv[j + 1] = idxv[j]; ord[j + 1] = ord[j]; j--;
        }
        idxv[j + 1] = kv; ord[j + 1] = ko;
    }
    for (unsigned r = 0; r < c; r++) {
        ((float4*)out)[F + r] = b_pay[s + ord[r]];
        if (writeValid) validOut[F + r] = 1.f;
    }
}

// ---------------- launch (4 kernels) ----------------
extern "C" void kernel_launch(void* const* d_in, const int* in_sizes, int n_in,
                              void* d_out, int out_size) {
    const float* vol = (const float*)d_in[0];
    float* out = (float*)d_out;
    int writeValid = (out_size >= KPK * 5) ? 1 : 0;
    float* validOut = out + (size_t)KPK * 4;

    k_detect<<<4096, 256>>>(vol);
    k_verify_cent<<<CAND_CAP / 256, 256>>>(vol);
    k_scan<<<NCH, 256>>>();
    k_finalize<<<NBLK_BUCKET + NBLK_PAD, 256>>>(out, validOut, writeValid);
}